// round 1
// baseline (speedup 1.0000x reference)
#include <cuda_runtime.h>

// Problem constants
#define BATCH 8
#define NTOK  4096      // H*W = 64*64
#define DIM   128       // C == HC
#define BM    64        // query tile rows
#define BN    64        // key tile rows

// -------- scratch (no cudaMalloc allowed) --------
__device__ float g_q[BATCH * NTOK * DIM];
__device__ float g_k[BATCH * NTOK * DIM];
__device__ float g_v[BATCH * NTOK * DIM];
__device__ float g_att[BATCH * NTOK * DIM];

// XOR swizzle on float4 granularity: element (row r, float4-col c4) of a
// [64][128]-float tile lives at float4 index r*32 + (c4 ^ ((r>>2)&7)).
// This makes "16 threads read 16 different rows at the same logical c4"
// hit 8 distinct bank groups (2-way) instead of 1 (16-way).
__device__ __forceinline__ int swz(int r, int c4) {
    return r * 32 + (c4 ^ ((r >> 2) & 7));
}

// ============================================================================
// Kernel 1: fused QKV projection.  grid = (B*N/16), block = 128.
// Each block: 16 rows of x; thread j owns output column j for q,k,v.
// ============================================================================
__global__ void qkv_kernel(const float* __restrict__ x,
                           const float* __restrict__ wq, const float* __restrict__ bq,
                           const float* __restrict__ wk, const float* __restrict__ bk,
                           const float* __restrict__ wv, const float* __restrict__ bv) {
    __shared__ float xs[16][DIM];
    const int tid = threadIdx.x;                 // 0..127
    const long row0 = (long)blockIdx.x * 16;

    // cooperative load of 16x128 x tile (float4)
    const float4* x4 = (const float4*)(x + row0 * DIM);
    float4* xs4 = (float4*)&xs[0][0];
#pragma unroll
    for (int i = 0; i < 4; i++) xs4[tid + i * 128] = x4[tid + i * 128];
    __syncthreads();

    float aq[16], ak[16], av[16];
#pragma unroll
    for (int r = 0; r < 16; r++) { aq[r] = 0.f; ak[r] = 0.f; av[r] = 0.f; }

    const int j = tid;
#pragma unroll 4
    for (int c = 0; c < DIM; c++) {
        const float wqc = wq[c * DIM + j];
        const float wkc = wk[c * DIM + j];
        const float wvc = wv[c * DIM + j];
#pragma unroll
        for (int r = 0; r < 16; r++) {
            const float xv = xs[r][c];
            aq[r] = fmaf(xv, wqc, aq[r]);
            ak[r] = fmaf(xv, wkc, ak[r]);
            av[r] = fmaf(xv, wvc, av[r]);
        }
    }
    const float bqj = bq[j], bkj = bk[j], bvj = bv[j];
#pragma unroll
    for (int r = 0; r < 16; r++) {
        const long o = (row0 + r) * DIM + j;
        g_q[o] = aq[r] + bqj;
        g_k[o] = ak[r] + bkj;
        g_v[o] = av[r] + bvj;
    }
}

// ============================================================================
// Kernel 2: flash attention (unscaled scores), fp32.
// grid = (N/BM, B), block = 256 threads, 2 blocks/SM.
// smem: Qs[64][128] (swizzled), KVs[64][128] (swizzled; K then reused for V),
//       Ss[64][68], m/l/scale[64].
// ============================================================================
#define SPAD 68
#define SM_FLOATS (64 * 128 + 64 * 128 + 64 * SPAD + 3 * 64)

__global__ __launch_bounds__(256, 2) void attn_kernel() {
    extern __shared__ float sm[];
    float*  Qs  = sm;                          // 8192 floats
    float*  KVs = sm + 64 * 128;               // 8192 floats
    float*  Ss  = sm + 2 * 64 * 128;           // 64*68 floats
    float*  m_s = Ss + 64 * SPAD;
    float*  l_s = m_s + 64;
    float*  sc_s = l_s + 64;
    float4* Qs4  = (float4*)Qs;
    float4* KVs4 = (float4*)KVs;

    const int tid = threadIdx.x;
    const int b  = blockIdx.y;
    const int qt = blockIdx.x;

    const float* qbase = g_q + ((long)b * NTOK + (long)qt * BM) * DIM;
    const float* kbase = g_k + (long)b * NTOK * DIM;
    const float* vbase = g_v + (long)b * NTOK * DIM;

    // ---- load Q tile (swizzled) ----
    {
        const float4* q4 = (const float4*)qbase;
#pragma unroll
        for (int i = 0; i < 8; i++) {
            const int idx = tid + i * 256;        // 0..2047
            const int r = idx >> 5, c4 = idx & 31;
            Qs4[swz(r, c4)] = q4[idx];
        }
    }
    if (tid < 64) { m_s[tid] = -1e30f; l_s[tid] = 0.f; }

    // S-compute / PV mapping: 16x16 thread grid
    const int tr = tid >> 4;          // 0..15 -> rows tr*4..tr*4+3
    const int tc = tid & 15;          // 0..15
    // PV columns: split pair of float4s to avoid 4-way LDS conflicts
    const int c0 = tc * 4;            // cols c0..c0+3
    const int c1 = 64 + tc * 4;       // cols c1..c1+3
    // softmax mapping: 4 threads per row
    const int sr = tid >> 2;          // 0..63
    const int sg = tid & 3;           // 0..3 -> cols sg*16..sg*16+15

    float o[4][8];
#pragma unroll
    for (int i = 0; i < 4; i++)
#pragma unroll
        for (int j = 0; j < 8; j++) o[i][j] = 0.f;

    __syncthreads();

    for (int t = 0; t < NTOK / BN; t++) {
        // ---- load K tile ----
        {
            const float4* k4 = (const float4*)(kbase + (long)t * BN * DIM);
#pragma unroll
            for (int i = 0; i < 8; i++) {
                const int idx = tid + i * 256;
                const int r = idx >> 5, c4 = idx & 31;
                KVs4[swz(r, c4)] = k4[idx];
            }
        }
        __syncthreads();

        // ---- S = Q K^T (4x4 per thread) ----
        {
            float acc[4][4];
#pragma unroll
            for (int i = 0; i < 4; i++)
#pragma unroll
                for (int j = 0; j < 4; j++) acc[i][j] = 0.f;

#pragma unroll 4
            for (int d4 = 0; d4 < 32; d4++) {
                float4 qv[4], kv[4];
#pragma unroll
                for (int i = 0; i < 4; i++) qv[i] = Qs4[swz(tr * 4 + i, d4)];
#pragma unroll
                for (int j = 0; j < 4; j++) kv[j] = KVs4[swz(tc * 4 + j, d4)];
#pragma unroll
                for (int i = 0; i < 4; i++)
#pragma unroll
                    for (int j = 0; j < 4; j++) {
                        acc[i][j] = fmaf(qv[i].x, kv[j].x, acc[i][j]);
                        acc[i][j] = fmaf(qv[i].y, kv[j].y, acc[i][j]);
                        acc[i][j] = fmaf(qv[i].z, kv[j].z, acc[i][j]);
                        acc[i][j] = fmaf(qv[i].w, kv[j].w, acc[i][j]);
                    }
            }
#pragma unroll
            for (int i = 0; i < 4; i++)
                *(float4*)&Ss[(tr * 4 + i) * SPAD + tc * 4] =
                    make_float4(acc[i][0], acc[i][1], acc[i][2], acc[i][3]);
        }
        __syncthreads();   // S done; K reads done

        // ---- prefetch V into registers (overlaps softmax latency) ----
        float4 vreg[8];
        {
            const float4* v4 = (const float4*)(vbase + (long)t * BN * DIM);
#pragma unroll
            for (int i = 0; i < 8; i++) vreg[i] = v4[tid + i * 256];
        }

        // ---- online softmax for row sr, chunk sg ----
        {
            const float mold = m_s[sr];
            float sv[16];
            float tmax = -1e30f;
#pragma unroll
            for (int k = 0; k < 16; k++) {
                sv[k] = Ss[sr * SPAD + sg * 16 + k];
                tmax = fmaxf(tmax, sv[k]);
            }
            tmax = fmaxf(tmax, __shfl_xor_sync(0xffffffffu, tmax, 1));
            tmax = fmaxf(tmax, __shfl_xor_sync(0xffffffffu, tmax, 2));
            const float mnew = fmaxf(mold, tmax);
            float rsum = 0.f;
#pragma unroll
            for (int k = 0; k < 16; k++) {
                const float p = __expf(sv[k] - mnew);
                Ss[sr * SPAD + sg * 16 + k] = p;
                rsum += p;
            }
            rsum += __shfl_xor_sync(0xffffffffu, rsum, 1);
            rsum += __shfl_xor_sync(0xffffffffu, rsum, 2);
            if (sg == 0) {
                const float sc = __expf(mold - mnew);
                sc_s[sr] = sc;
                l_s[sr] = l_s[sr] * sc + rsum;
                m_s[sr] = mnew;
            }
        }

        // ---- store V into KVs (K reads finished at the last sync) ----
#pragma unroll
        for (int i = 0; i < 8; i++) {
            const int idx = tid + i * 256;
            const int r = idx >> 5, c4 = idx & 31;
            KVs4[swz(r, c4)] = vreg[i];
        }
        __syncthreads();   // V + p + scale all visible

        // ---- rescale O by exp(m_old - m_new) ----
        {
            float scr[4];
#pragma unroll
            for (int i = 0; i < 4; i++) scr[i] = sc_s[tr * 4 + i];
#pragma unroll
            for (int i = 0; i < 4; i++)
#pragma unroll
                for (int j = 0; j < 8; j++) o[i][j] *= scr[i];
        }

        // ---- O += P V ----
#pragma unroll 8
        for (int kk = 0; kk < BN; kk++) {
            const float p0 = Ss[(tr * 4 + 0) * SPAD + kk];
            const float p1 = Ss[(tr * 4 + 1) * SPAD + kk];
            const float p2 = Ss[(tr * 4 + 2) * SPAD + kk];
            const float p3 = Ss[(tr * 4 + 3) * SPAD + kk];
            const float4 va = KVs4[swz(kk, tc)];
            const float4 vb = KVs4[swz(kk, 16 + tc)];
            o[0][0] = fmaf(p0, va.x, o[0][0]); o[0][1] = fmaf(p0, va.y, o[0][1]);
            o[0][2] = fmaf(p0, va.z, o[0][2]); o[0][3] = fmaf(p0, va.w, o[0][3]);
            o[0][4] = fmaf(p0, vb.x, o[0][4]); o[0][5] = fmaf(p0, vb.y, o[0][5]);
            o[0][6] = fmaf(p0, vb.z, o[0][6]); o[0][7] = fmaf(p0, vb.w, o[0][7]);
            o[1][0] = fmaf(p1, va.x, o[1][0]); o[1][1] = fmaf(p1, va.y, o[1][1]);
            o[1][2] = fmaf(p1, va.z, o[1][2]); o[1][3] = fmaf(p1, va.w, o[1][3]);
            o[1][4] = fmaf(p1, vb.x, o[1][4]); o[1][5] = fmaf(p1, vb.y, o[1][5]);
            o[1][6] = fmaf(p1, vb.z, o[1][6]); o[1][7] = fmaf(p1, vb.w, o[1][7]);
            o[2][0] = fmaf(p2, va.x, o[2][0]); o[2][1] = fmaf(p2, va.y, o[2][1]);
            o[2][2] = fmaf(p2, va.z, o[2][2]); o[2][3] = fmaf(p2, va.w, o[2][3]);
            o[2][4] = fmaf(p2, vb.x, o[2][4]); o[2][5] = fmaf(p2, vb.y, o[2][5]);
            o[2][6] = fmaf(p2, vb.z, o[2][6]); o[2][7] = fmaf(p2, vb.w, o[2][7]);
            o[3][0] = fmaf(p3, va.x, o[3][0]); o[3][1] = fmaf(p3, va.y, o[3][1]);
            o[3][2] = fmaf(p3, va.z, o[3][2]); o[3][3] = fmaf(p3, va.w, o[3][3]);
            o[3][4] = fmaf(p3, vb.x, o[3][4]); o[3][5] = fmaf(p3, vb.y, o[3][5]);
            o[3][6] = fmaf(p3, vb.z, o[3][6]); o[3][7] = fmaf(p3, vb.w, o[3][7]);
        }
        __syncthreads();   // done with KVs/Ss before next tile overwrites
    }

    // ---- epilogue: divide by l, write attended ----
    {
        float rl[4];
#pragma unroll
        for (int i = 0; i < 4; i++) rl[i] = 1.f / l_s[tr * 4 + i];
        float* abase = g_att + ((long)b * NTOK + (long)qt * BM) * DIM;
#pragma unroll
        for (int i = 0; i < 4; i++) {
            float* row = abase + (tr * 4 + i) * DIM;
            row[c0 + 0] = o[i][0] * rl[i];
            row[c0 + 1] = o[i][1] * rl[i];
            row[c0 + 2] = o[i][2] * rl[i];
            row[c0 + 3] = o[i][3] * rl[i];
            row[c1 + 0] = o[i][4] * rl[i];
            row[c1 + 1] = o[i][5] * rl[i];
            row[c1 + 2] = o[i][6] * rl[i];
            row[c1 + 3] = o[i][7] * rl[i];
        }
    }
}

// ============================================================================
// Kernel 3: output projection + residual + relu.  grid = (B*N/16), block = 128.
// ============================================================================
__global__ void proj_kernel(const float* __restrict__ x,
                            const float* __restrict__ wp,
                            const float* __restrict__ bp,
                            float* __restrict__ out) {
    __shared__ float as[16][DIM];
    const int tid = threadIdx.x;
    const long row0 = (long)blockIdx.x * 16;

    const float4* a4 = (const float4*)(g_att + row0 * DIM);
    float4* as4 = (float4*)&as[0][0];
#pragma unroll
    for (int i = 0; i < 4; i++) as4[tid + i * 128] = a4[tid + i * 128];
    __syncthreads();

    float acc[16];
#pragma unroll
    for (int r = 0; r < 16; r++) acc[r] = 0.f;

    const int j = tid;
#pragma unroll 4
    for (int c = 0; c < DIM; c++) {
        const float wpc = wp[c * DIM + j];
#pragma unroll
        for (int r = 0; r < 16; r++) acc[r] = fmaf(as[r][c], wpc, acc[r]);
    }
    const float bpj = bp[j];
#pragma unroll
    for (int r = 0; r < 16; r++) {
        const long off = (row0 + r) * DIM + j;
        out[off] = fmaxf(x[off] + acc[r] + bpj, 0.f);
    }
}

// ============================================================================
// launch
// ============================================================================
extern "C" void kernel_launch(void* const* d_in, const int* in_sizes, int n_in,
                              void* d_out, int out_size) {
    (void)in_sizes; (void)n_in; (void)out_size;
    const float* x  = (const float*)d_in[0];
    const float* wq = (const float*)d_in[1];
    const float* bq = (const float*)d_in[2];
    const float* wk = (const float*)d_in[3];
    const float* bk = (const float*)d_in[4];
    const float* wv = (const float*)d_in[5];
    const float* bv = (const float*)d_in[6];
    const float* wp = (const float*)d_in[7];
    const float* bp = (const float*)d_in[8];
    float* out = (float*)d_out;

    const size_t smem = SM_FLOATS * sizeof(float);
    cudaFuncSetAttribute(attn_kernel,
                         cudaFuncAttributeMaxDynamicSharedMemorySize, (int)smem);

    qkv_kernel<<<BATCH * NTOK / 16, 128>>>(x, wq, bq, wk, bk, wv, bv);
    attn_kernel<<<dim3(NTOK / BM, BATCH), 256, smem>>>();
    proj_kernel<<<BATCH * NTOK / 16, 128>>>(x, wp, bp, out);
}

// round 2
// speedup vs baseline: 2.9969x; 2.9969x over previous
#include <cuda_runtime.h>
#include <cuda_bf16.h>
#include <cstdint>

#define BATCH 8
#define NTOK  4096
#define DIM   128
#define BM    128       // query rows per block (8 warps x 16)
#define BN    64        // kv rows per tile

typedef __nv_bfloat16 bf16;

// ---------------- scratch (no cudaMalloc allowed) ----------------
__device__ __align__(256) bf16 g_qhi[BATCH * NTOK * DIM];
__device__ __align__(256) bf16 g_qlo[BATCH * NTOK * DIM];
__device__ __align__(256) bf16 g_khi[BATCH * NTOK * DIM];
__device__ __align__(256) bf16 g_klo[BATCH * NTOK * DIM];
__device__ __align__(256) bf16 g_vhi[BATCH * NTOK * DIM];
__device__ __align__(256) bf16 g_vlo[BATCH * NTOK * DIM];
__device__ __align__(256) float g_att[BATCH * NTOK * DIM];

// ---------------- PTX helpers ----------------
__device__ __forceinline__ unsigned smem_u32(const void* p) {
    return (unsigned)__cvta_generic_to_shared(p);
}
__device__ __forceinline__ void cp_async16(unsigned saddr, const void* g) {
    asm volatile("cp.async.cg.shared.global [%0], [%1], 16;" :: "r"(saddr), "l"(g));
}
__device__ __forceinline__ void cp_commit() {
    asm volatile("cp.async.commit_group;");
}
__device__ __forceinline__ void cp_wait0() {
    asm volatile("cp.async.wait_group 0;");
}
__device__ __forceinline__ void ldsm4(unsigned addr, unsigned& r0, unsigned& r1,
                                      unsigned& r2, unsigned& r3) {
    asm volatile("ldmatrix.sync.aligned.m8n8.x4.shared.b16 {%0,%1,%2,%3}, [%4];"
                 : "=r"(r0), "=r"(r1), "=r"(r2), "=r"(r3) : "r"(addr));
}
__device__ __forceinline__ void ldsm4t(unsigned addr, unsigned& r0, unsigned& r1,
                                       unsigned& r2, unsigned& r3) {
    asm volatile("ldmatrix.sync.aligned.m8n8.x4.trans.shared.b16 {%0,%1,%2,%3}, [%4];"
                 : "=r"(r0), "=r"(r1), "=r"(r2), "=r"(r3) : "r"(addr));
}
__device__ __forceinline__ void mma16816(float* d, unsigned a0, unsigned a1,
                                         unsigned a2, unsigned a3,
                                         unsigned b0, unsigned b1) {
    asm volatile(
        "mma.sync.aligned.m16n8k16.row.col.f32.bf16.bf16.f32 "
        "{%0,%1,%2,%3}, {%4,%5,%6,%7}, {%8,%9}, {%0,%1,%2,%3};"
        : "+f"(d[0]), "+f"(d[1]), "+f"(d[2]), "+f"(d[3])
        : "r"(a0), "r"(a1), "r"(a2), "r"(a3), "r"(b0), "r"(b1));
}
__device__ __forceinline__ unsigned pack_bf16(bf16 a, bf16 b) {
    return (unsigned)__bfloat16_as_ushort(a) |
           ((unsigned)__bfloat16_as_ushort(b) << 16);
}

// swizzled byte offset inside a [rows][128] bf16 tile (256B rows, 16B chunks)
__device__ __forceinline__ unsigned tswz(int r, int chunk) {
    return (unsigned)(r * 256 + ((chunk ^ (r & 7)) << 4));
}

// ============================================================================
// Kernel 1: fused QKV projection -> bf16 hi/lo outputs.
// grid = B*N/16, block = 128
// ============================================================================
__global__ void qkv_kernel(const float* __restrict__ x,
                           const float* __restrict__ wq, const float* __restrict__ bq,
                           const float* __restrict__ wk, const float* __restrict__ bk,
                           const float* __restrict__ wv, const float* __restrict__ bv) {
    __shared__ float xs[16][DIM];
    const int tid = threadIdx.x;
    const long row0 = (long)blockIdx.x * 16;

    const float4* x4 = (const float4*)(x + row0 * DIM);
    float4* xs4 = (float4*)&xs[0][0];
#pragma unroll
    for (int i = 0; i < 4; i++) xs4[tid + i * 128] = x4[tid + i * 128];
    __syncthreads();

    float aq[16], ak[16], av[16];
#pragma unroll
    for (int r = 0; r < 16; r++) { aq[r] = 0.f; ak[r] = 0.f; av[r] = 0.f; }

    const int j = tid;
#pragma unroll 4
    for (int c = 0; c < DIM; c++) {
        const float wqc = wq[c * DIM + j];
        const float wkc = wk[c * DIM + j];
        const float wvc = wv[c * DIM + j];
#pragma unroll
        for (int r = 0; r < 16; r++) {
            const float xv = xs[r][c];
            aq[r] = fmaf(xv, wqc, aq[r]);
            ak[r] = fmaf(xv, wkc, ak[r]);
            av[r] = fmaf(xv, wvc, av[r]);
        }
    }
    const float bqj = bq[j], bkj = bk[j], bvj = bv[j];
#pragma unroll
    for (int r = 0; r < 16; r++) {
        const long o = (row0 + r) * DIM + j;
        const float q = aq[r] + bqj, k = ak[r] + bkj, v = av[r] + bvj;
        const bf16 qh = __float2bfloat16_rn(q);
        const bf16 kh = __float2bfloat16_rn(k);
        const bf16 vh = __float2bfloat16_rn(v);
        g_qhi[o] = qh; g_qlo[o] = __float2bfloat16_rn(q - __bfloat162float(qh));
        g_khi[o] = kh; g_klo[o] = __float2bfloat16_rn(k - __bfloat162float(kh));
        g_vhi[o] = vh; g_vlo[o] = __float2bfloat16_rn(v - __bfloat162float(vh));
    }
}

// ============================================================================
// Kernel 2: flash attention, bf16x3 tensor-core emulation of fp32.
// grid = (N/BM=32, B=8), block = 256 (8 warps), 1 CTA/SM.
// smem: Qhi/Qlo [128][128] + 2 stages of {Khi,Klo,Vhi,Vlo}[64][128]  = 192KB
// ============================================================================
#define QHI_OFF   0
#define QLO_OFF   32768
#define STAGE_OFF 65536
#define STAGE_SZ  65536
#define ARR_SZ    16384   // one 64x128 bf16 tile
#define SMEM_BYTES (STAGE_OFF + 2 * STAGE_SZ)

__global__ __launch_bounds__(256) void attn_kernel() {
    extern __shared__ char sm[];
    const unsigned sbase = smem_u32(sm);

    const int tid  = threadIdx.x;
    const int lane = tid & 31;
    const int w    = tid >> 5;           // warp 0..7
    const int b    = blockIdx.y;
    const int qt   = blockIdx.x;
    const long batch_off = (long)b * NTOK * DIM;
    const long q_off = batch_off + (long)qt * BM * DIM;

    // ---- prologue: cp.async Q tile (hi+lo) and KV tile 0 ----
    {
        // Q: 2 arrays x 128 rows x 16 chunks = 4096 chunks
        const bf16* gq[2] = { g_qhi + q_off, g_qlo + q_off };
#pragma unroll
        for (int i = 0; i < 16; i++) {
            const int idx = tid + i * 256;
            const int arr = idx >> 11;
            const int wi  = idx & 2047;
            const int r = wi >> 4, c = wi & 15;
            cp_async16(sbase + (arr ? QLO_OFF : QHI_OFF) + tswz(r, c),
                       gq[arr] + r * DIM + c * 8);
        }
        // KV tile 0
        const bf16* gkv[4] = { g_khi + batch_off, g_klo + batch_off,
                               g_vhi + batch_off, g_vlo + batch_off };
#pragma unroll
        for (int i = 0; i < 16; i++) {
            const int idx = tid + i * 256;
            const int arr = idx >> 10;
            const int wi  = idx & 1023;
            const int r = wi >> 4, c = wi & 15;
            cp_async16(sbase + STAGE_OFF + arr * ARR_SZ + tswz(r, c),
                       gkv[arr] + r * DIM + c * 8);
        }
        cp_commit();
    }

    // per-lane ldmatrix address components
    const int m0 = w * 16;
    const int qrow   = m0 + (lane & 15);
    const int qchoff = lane >> 4;                        // 0/1 -> +8 k cols
    const unsigned qrow_base = (unsigned)(qrow * 256);
    const int qsw = qrow & 7;

    const int krow_off = (lane & 7) + ((lane >> 4) << 3); // K row within 16-blk
    const int kchoff   = (lane >> 3) & 1;
    const int vrow_off = (lane & 7) + (((lane >> 3) & 1) << 3);
    const int vchoff   = lane >> 4;

    // softmax state (rows r1 = m0+g, r2 = r1+8)
    float mrow1 = -1e30f, mrow2 = -1e30f, lrow1 = 0.f, lrow2 = 0.f;

    float o[16][4];
#pragma unroll
    for (int i = 0; i < 16; i++)
#pragma unroll
        for (int jj = 0; jj < 4; jj++) o[i][jj] = 0.f;

    for (int t = 0; t < NTOK / BN; t++) {
        cp_wait0();
        __syncthreads();

        const unsigned cur = STAGE_OFF + (unsigned)(t & 1) * STAGE_SZ;

        // issue next tile into the other stage
        if (t + 1 < NTOK / BN) {
            const unsigned nxt = STAGE_OFF + (unsigned)((t + 1) & 1) * STAGE_SZ;
            const long kv_off = batch_off + (long)(t + 1) * BN * DIM;
            const bf16* gkv[4] = { g_khi + kv_off, g_klo + kv_off,
                                   g_vhi + kv_off, g_vlo + kv_off };
#pragma unroll
            for (int i = 0; i < 16; i++) {
                const int idx = tid + i * 256;
                const int arr = idx >> 10;
                const int wi  = idx & 1023;
                const int r = wi >> 4, c = wi & 15;
                cp_async16(sbase + nxt + arr * ARR_SZ + tswz(r, c),
                           gkv[arr] + r * DIM + c * 8);
            }
            cp_commit();
        }

        const unsigned KHI = cur, KLO = cur + ARR_SZ;
        const unsigned VHI = cur + 2 * ARR_SZ, VLO = cur + 3 * ARR_SZ;

        // ---- S = Q K^T  (bf16x3) ----
        float s[8][4];
#pragma unroll
        for (int i = 0; i < 8; i++)
#pragma unroll
            for (int jj = 0; jj < 4; jj++) s[i][jj] = 0.f;

#pragma unroll
        for (int k = 0; k < 8; k++) {
            unsigned ah0, ah1, ah2, ah3, al0, al1, al2, al3;
            {
                const unsigned ch = (unsigned)(((2 * k + qchoff) ^ qsw) << 4);
                ldsm4(sbase + QHI_OFF + qrow_base + ch, ah0, ah1, ah2, ah3);
                ldsm4(sbase + QLO_OFF + qrow_base + ch, al0, al1, al2, al3);
            }
#pragma unroll
            for (int nb = 0; nb < 4; nb++) {
                const int krow = nb * 16 + krow_off;
                const unsigned koff = tswz(krow, 2 * k + kchoff);
                unsigned bh0, bh1, bh2, bh3, bl0, bl1, bl2, bl3;
                ldsm4(sbase + KHI + koff, bh0, bh1, bh2, bh3);
                ldsm4(sbase + KLO + koff, bl0, bl1, bl2, bl3);
                mma16816(s[2 * nb],     ah0, ah1, ah2, ah3, bh0, bh1);
                mma16816(s[2 * nb],     ah0, ah1, ah2, ah3, bl0, bl1);
                mma16816(s[2 * nb],     al0, al1, al2, al3, bh0, bh1);
                mma16816(s[2 * nb + 1], ah0, ah1, ah2, ah3, bh2, bh3);
                mma16816(s[2 * nb + 1], ah0, ah1, ah2, ah3, bl2, bl3);
                mma16816(s[2 * nb + 1], al0, al1, al2, al3, bh2, bh3);
            }
        }

        // ---- online softmax (warp-local; rows r1, r2) ----
        float rm1 = -1e30f, rm2 = -1e30f;
#pragma unroll
        for (int i = 0; i < 8; i++) {
            rm1 = fmaxf(rm1, fmaxf(s[i][0], s[i][1]));
            rm2 = fmaxf(rm2, fmaxf(s[i][2], s[i][3]));
        }
        rm1 = fmaxf(rm1, __shfl_xor_sync(0xffffffffu, rm1, 1));
        rm1 = fmaxf(rm1, __shfl_xor_sync(0xffffffffu, rm1, 2));
        rm2 = fmaxf(rm2, __shfl_xor_sync(0xffffffffu, rm2, 1));
        rm2 = fmaxf(rm2, __shfl_xor_sync(0xffffffffu, rm2, 2));

        const float mn1 = fmaxf(mrow1, rm1), mn2 = fmaxf(mrow2, rm2);
        const float sc1 = __expf(mrow1 - mn1), sc2 = __expf(mrow2 - mn2);
        mrow1 = mn1; mrow2 = mn2;

        float rs1 = 0.f, rs2 = 0.f;
#pragma unroll
        for (int i = 0; i < 8; i++) {
            s[i][0] = __expf(s[i][0] - mn1); rs1 += s[i][0];
            s[i][1] = __expf(s[i][1] - mn1); rs1 += s[i][1];
            s[i][2] = __expf(s[i][2] - mn2); rs2 += s[i][2];
            s[i][3] = __expf(s[i][3] - mn2); rs2 += s[i][3];
        }
        rs1 += __shfl_xor_sync(0xffffffffu, rs1, 1);
        rs1 += __shfl_xor_sync(0xffffffffu, rs1, 2);
        rs2 += __shfl_xor_sync(0xffffffffu, rs2, 1);
        rs2 += __shfl_xor_sync(0xffffffffu, rs2, 2);
        lrow1 = lrow1 * sc1 + rs1;
        lrow2 = lrow2 * sc2 + rs2;

        // rescale O
#pragma unroll
        for (int i = 0; i < 16; i++) {
            o[i][0] *= sc1; o[i][1] *= sc1;
            o[i][2] *= sc2; o[i][3] *= sc2;
        }

        // ---- O += P V  (bf16x3) ----
#pragma unroll
        for (int kp = 0; kp < 4; kp++) {
            // P frags (hi/lo) from s[2kp], s[2kp+1]
            unsigned pah[4], pal[4];
#pragma unroll
            for (int h = 0; h < 2; h++) {       // h=0: cols +0..7 -> a0,a1 ; h=1 -> a2,a3
                const float p0 = s[2 * kp + h][0], p1 = s[2 * kp + h][1];
                const float p2 = s[2 * kp + h][2], p3 = s[2 * kp + h][3];
                const bf16 h0 = __float2bfloat16_rn(p0), h1 = __float2bfloat16_rn(p1);
                const bf16 h2 = __float2bfloat16_rn(p2), h3 = __float2bfloat16_rn(p3);
                pah[2 * h]     = pack_bf16(h0, h1);
                pah[2 * h + 1] = pack_bf16(h2, h3);
                pal[2 * h]     = pack_bf16(
                    __float2bfloat16_rn(p0 - __bfloat162float(h0)),
                    __float2bfloat16_rn(p1 - __bfloat162float(h1)));
                pal[2 * h + 1] = pack_bf16(
                    __float2bfloat16_rn(p2 - __bfloat162float(h2)),
                    __float2bfloat16_rn(p3 - __bfloat162float(h3)));
            }
#pragma unroll
            for (int n16 = 0; n16 < 8; n16++) {
                const int vrow = kp * 16 + vrow_off;
                const unsigned voff = tswz(vrow, 2 * n16 + vchoff);
                unsigned bh0, bh1, bh2, bh3, bl0, bl1, bl2, bl3;
                ldsm4t(sbase + VHI + voff, bh0, bh1, bh2, bh3);
                ldsm4t(sbase + VLO + voff, bl0, bl1, bl2, bl3);
                mma16816(o[2 * n16],     pah[0], pah[1], pah[2], pah[3], bh0, bh1);
                mma16816(o[2 * n16],     pah[0], pah[1], pah[2], pah[3], bl0, bl1);
                mma16816(o[2 * n16],     pal[0], pal[1], pal[2], pal[3], bh0, bh1);
                mma16816(o[2 * n16 + 1], pah[0], pah[1], pah[2], pah[3], bh2, bh3);
                mma16816(o[2 * n16 + 1], pah[0], pah[1], pah[2], pah[3], bl2, bl3);
                mma16816(o[2 * n16 + 1], pal[0], pal[1], pal[2], pal[3], bh2, bh3);
            }
        }
        __syncthreads();   // all warps done with cur stage before it is refilled
    }

    // ---- epilogue: normalize and store ----
    const float rl1 = 1.f / lrow1, rl2 = 1.f / lrow2;
    const int g = lane >> 2, tig = lane & 3;
    const long row1 = (long)b * NTOK + (long)qt * BM + m0 + g;
    const long row2 = row1 + 8;
#pragma unroll
    for (int i = 0; i < 16; i++) {
        const int col = i * 8 + 2 * tig;
        float2 v1 = make_float2(o[i][0] * rl1, o[i][1] * rl1);
        float2 v2 = make_float2(o[i][2] * rl2, o[i][3] * rl2);
        *(float2*)&g_att[row1 * DIM + col] = v1;
        *(float2*)&g_att[row2 * DIM + col] = v2;
    }
}

// ============================================================================
// Kernel 3: output projection + residual + relu
// ============================================================================
__global__ void proj_kernel(const float* __restrict__ x,
                            const float* __restrict__ wp,
                            const float* __restrict__ bp,
                            float* __restrict__ out) {
    __shared__ float as[16][DIM];
    const int tid = threadIdx.x;
    const long row0 = (long)blockIdx.x * 16;

    const float4* a4 = (const float4*)(g_att + row0 * DIM);
    float4* as4 = (float4*)&as[0][0];
#pragma unroll
    for (int i = 0; i < 4; i++) as4[tid + i * 128] = a4[tid + i * 128];
    __syncthreads();

    float acc[16];
#pragma unroll
    for (int r = 0; r < 16; r++) acc[r] = 0.f;

    const int j = tid;
#pragma unroll 4
    for (int c = 0; c < DIM; c++) {
        const float wpc = wp[c * DIM + j];
#pragma unroll
        for (int r = 0; r < 16; r++) acc[r] = fmaf(as[r][c], wpc, acc[r]);
    }
    const float bpj = bp[j];
#pragma unroll
    for (int r = 0; r < 16; r++) {
        const long off = (row0 + r) * DIM + j;
        out[off] = fmaxf(x[off] + acc[r] + bpj, 0.f);
    }
}

// ============================================================================
// launch
// ============================================================================
extern "C" void kernel_launch(void* const* d_in, const int* in_sizes, int n_in,
                              void* d_out, int out_size) {
    (void)in_sizes; (void)n_in; (void)out_size;
    const float* x  = (const float*)d_in[0];
    const float* wq = (const float*)d_in[1];
    const float* bq = (const float*)d_in[2];
    const float* wk = (const float*)d_in[3];
    const float* bk = (const float*)d_in[4];
    const float* wv = (const float*)d_in[5];
    const float* bv = (const float*)d_in[6];
    const float* wp = (const float*)d_in[7];
    const float* bp = (const float*)d_in[8];
    float* out = (float*)d_out;

    cudaFuncSetAttribute(attn_kernel,
                         cudaFuncAttributeMaxDynamicSharedMemorySize, SMEM_BYTES);

    qkv_kernel<<<BATCH * NTOK / 16, 128>>>(x, wq, bq, wk, bk, wv, bv);
    attn_kernel<<<dim3(NTOK / BM, BATCH), 256, SMEM_BYTES>>>();
    proj_kernel<<<BATCH * NTOK / 16, 128>>>(x, wp, bp, out);
}